// round 2
// baseline (speedup 1.0000x reference)
#include <cuda_runtime.h>
#include <cstdint>

// Problem dims
#define NB 128        // batch
#define NS 256        // seq len
#define NH 1024       // hidden
#define NE 512        // embed
#define NV 32000      // vocab
#define NL 2          // layers

// Output packing (prediction, new_hidden, new_cell, attn) in float32
#define OFF_PRED 0
#define OFF_HID  (NB*NV)                  // 4096000
#define OFF_CELL (OFF_HID + NL*NB*NH)     // 4358144
#define OFF_ATTN (OFF_CELL + NL*NB*NH)    // 4620288

// -------- device scratch (no allocations allowed) --------
__device__ float g_q[NB*NH];              // W2 query
__device__ float g_spart[8*NB*NS];        // per-N-block score partials (8 col-blocks)
__device__ float g_scores[NB*NS];
__device__ float g_context[NB*NH];
__device__ float g_x[NB*(NE+NH)];         // [emb, context]
__device__ float g_gates[NB*4*NH];
__device__ float g_cat2[NB*2*NH];         // [h1, context]

// -------- TF32 GEMM: C(M,N) = A(M,K) @ B(N,K)^T --------
#define BM 128
#define BN 128
#define BK 16
#define PADA 4

#define EPI_STORE 0
#define EPI_ADD   1
#define EPI_ATTN  2

__device__ __forceinline__ uint32_t f2tf(float x){
  uint32_t u; asm("cvt.rna.tf32.f32 %0, %1;" : "=r"(u) : "f"(x)); return u;
}

__device__ __forceinline__ void mma8(float* d, const uint32_t* a, const uint32_t* b){
  asm volatile("mma.sync.aligned.m16n8k8.row.col.f32.tf32.tf32.f32 "
    "{%0,%1,%2,%3},{%4,%5,%6,%7},{%8,%9},{%0,%1,%2,%3};"
    : "+f"(d[0]),"+f"(d[1]),"+f"(d[2]),"+f"(d[3])
    : "r"(a[0]),"r"(a[1]),"r"(a[2]),"r"(a[3]),"r"(b[0]),"r"(b[1]));
}

template<int EPI>
__global__ void __launch_bounds__(256,1) gemm_tf32(
    const float* __restrict__ A, const float* __restrict__ Bw, float* __restrict__ C,
    int M, int N, int K,
    const float* __restrict__ bias,
    const float* __restrict__ qv,      // ATTN: query (B,H)
    const float* __restrict__ vw,      // ATTN: V_w (H)
    float* __restrict__ spart)         // ATTN: partials [gridDim.x][M]
{
  __shared__ uint32_t As[2][BK][BM+PADA];
  __shared__ uint32_t Bs[2][BK][BN+PADA];
  __shared__ float srow[BM];

  const int tid  = threadIdx.x;
  const int m0   = blockIdx.y*BM, n0 = blockIdx.x*BN;
  const int warp = tid>>5, lane = tid&31;
  const int wm   = (warp>>1)*32, wn = (warp&1)*64;
  const int g    = lane>>2, tq = lane&3;

  const int frow = tid>>2;           // 0..63
  const int fcol = (tid&3)<<2;       // 0,4,8,12

  float acc[2][8][4];
  #pragma unroll
  for (int i=0;i<2;i++)
    #pragma unroll
    for (int j=0;j<8;j++)
      #pragma unroll
      for (int k=0;k<4;k++) acc[i][j][k]=0.f;

  const int ktiles = K/BK;

  // prologue: tile 0 -> buf 0
  #pragma unroll
  for (int i=0;i<2;i++){
    int row = frow + i*64;
    float4 av = *(const float4*)(A  + (size_t)(m0+row)*K + fcol);
    float4 bv = *(const float4*)(Bw + (size_t)(n0+row)*K + fcol);
    As[0][fcol+0][row]=f2tf(av.x); As[0][fcol+1][row]=f2tf(av.y);
    As[0][fcol+2][row]=f2tf(av.z); As[0][fcol+3][row]=f2tf(av.w);
    Bs[0][fcol+0][row]=f2tf(bv.x); Bs[0][fcol+1][row]=f2tf(bv.y);
    Bs[0][fcol+2][row]=f2tf(bv.z); Bs[0][fcol+3][row]=f2tf(bv.w);
  }
  __syncthreads();

  for (int kt=0; kt<ktiles; kt++){
    const int cur = kt&1;
    float4 ra[2], rb[2];
    const bool pf = (kt+1 < ktiles);
    if (pf){
      const int k0 = (kt+1)*BK + fcol;
      #pragma unroll
      for (int i=0;i<2;i++){
        int row = frow + i*64;
        ra[i] = *(const float4*)(A  + (size_t)(m0+row)*K + k0);
        rb[i] = *(const float4*)(Bw + (size_t)(n0+row)*K + k0);
      }
    }
    #pragma unroll
    for (int kk=0; kk<2; kk++){
      const int kb = kk*8;
      uint32_t af[2][4], bf[8][2];
      #pragma unroll
      for (int mt=0; mt<2; mt++){
        int r = wm + mt*16 + g;
        af[mt][0]=As[cur][kb+tq  ][r];
        af[mt][1]=As[cur][kb+tq  ][r+8];
        af[mt][2]=As[cur][kb+tq+4][r];
        af[mt][3]=As[cur][kb+tq+4][r+8];
      }
      #pragma unroll
      for (int nt=0; nt<8; nt++){
        int cn = wn + nt*8 + g;
        bf[nt][0]=Bs[cur][kb+tq  ][cn];
        bf[nt][1]=Bs[cur][kb+tq+4][cn];
      }
      #pragma unroll
      for (int mt=0; mt<2; mt++)
        #pragma unroll
        for (int nt=0; nt<8; nt++)
          mma8(acc[mt][nt], af[mt], bf[nt]);
    }
    if (pf){
      const int nb = cur^1;
      #pragma unroll
      for (int i=0;i<2;i++){
        int row = frow + i*64;
        As[nb][fcol+0][row]=f2tf(ra[i].x); As[nb][fcol+1][row]=f2tf(ra[i].y);
        As[nb][fcol+2][row]=f2tf(ra[i].z); As[nb][fcol+3][row]=f2tf(ra[i].w);
        Bs[nb][fcol+0][row]=f2tf(rb[i].x); Bs[nb][fcol+1][row]=f2tf(rb[i].y);
        Bs[nb][fcol+2][row]=f2tf(rb[i].z); Bs[nb][fcol+3][row]=f2tf(rb[i].w);
      }
      __syncthreads();
    }
  }

  if (EPI == EPI_ATTN){
    // energy = tanh(acc + W1_b[n] + q[b][n]); partial score = sum_n energy * Vw[n]
    if (tid < BM) srow[tid] = 0.f;
    __syncthreads();
    const float* qrow = qv + (size_t)(m0/NS)*NH;   // 128-row block lies within one batch b
    #pragma unroll
    for (int mt=0; mt<2; mt++){
      float p0=0.f, p1=0.f;
      #pragma unroll
      for (int nt=0; nt<8; nt++){
        int c = n0 + wn + nt*8 + 2*tq;
        float b0 = bias[c]   + qrow[c];
        float b1 = bias[c+1] + qrow[c+1];
        float v0 = vw[c], v1 = vw[c+1];
        p0 += tanhf(acc[mt][nt][0]+b0)*v0 + tanhf(acc[mt][nt][1]+b1)*v1;
        p1 += tanhf(acc[mt][nt][2]+b0)*v0 + tanhf(acc[mt][nt][3]+b1)*v1;
      }
      p0 += __shfl_xor_sync(0xffffffffu, p0, 1);
      p0 += __shfl_xor_sync(0xffffffffu, p0, 2);
      p1 += __shfl_xor_sync(0xffffffffu, p1, 1);
      p1 += __shfl_xor_sync(0xffffffffu, p1, 2);
      if (tq==0){
        atomicAdd(&srow[wm+mt*16+g  ], p0);   // exactly 2 adds/row -> order-invariant
        atomicAdd(&srow[wm+mt*16+g+8], p1);
      }
    }
    __syncthreads();
    if (tid < BM) spart[(size_t)blockIdx.x*M + m0 + tid] = srow[tid];
  } else {
    #pragma unroll
    for (int mt=0; mt<2; mt++){
      #pragma unroll
      for (int nt=0; nt<8; nt++){
        int r = m0 + wm + mt*16 + g;
        int c = n0 + wn + nt*8 + 2*tq;
        float b0 = bias ? bias[c]   : 0.f;
        float b1 = bias ? bias[c+1] : 0.f;
        float* p0 = C + (size_t)r*N + c;
        float* p1 = C + (size_t)(r+8)*N + c;
        if (EPI == EPI_STORE){
          p0[0]=acc[mt][nt][0]+b0; p0[1]=acc[mt][nt][1]+b1;
          p1[0]=acc[mt][nt][2]+b0; p1[1]=acc[mt][nt][3]+b1;
        } else {
          p0[0]+=acc[mt][nt][0]+b0; p0[1]+=acc[mt][nt][1]+b1;
          p1[0]+=acc[mt][nt][2]+b0; p1[1]+=acc[mt][nt][3]+b1;
        }
      }
    }
  }
}

// -------- small kernels --------

__global__ void reduce_scores_k(const float* __restrict__ spart,
                                const float* __restrict__ vb,
                                float* __restrict__ scores){
  int m = blockIdx.x*256 + threadIdx.x;
  float s = vb[0];
  #pragma unroll
  for (int j=0;j<8;j++) s += spart[(size_t)j*(NB*NS) + m];
  scores[m] = s;
}

__global__ void __launch_bounds__(NS) softmax_ctx_k(
    const float* __restrict__ scores, const float* __restrict__ enc,
    float* __restrict__ attn_out, float* __restrict__ ctx)
{
  __shared__ float sa[NS];
  __shared__ float red[8];
  const int b = blockIdx.x, tid = threadIdx.x;
  float v = scores[b*NS + tid];

  float m = v;
  #pragma unroll
  for (int o=16;o>0;o>>=1) m = fmaxf(m, __shfl_xor_sync(0xffffffffu, m, o));
  if ((tid&31)==0) red[tid>>5] = m;
  __syncthreads();
  if (tid==0){ float x=red[0]; for (int i=1;i<8;i++) x=fmaxf(x,red[i]); red[0]=x; }
  __syncthreads();
  const float bm = red[0];
  __syncthreads();

  float e = expf(v - bm);
  float s = e;
  #pragma unroll
  for (int o=16;o>0;o>>=1) s += __shfl_xor_sync(0xffffffffu, s, o);
  if ((tid&31)==0) red[tid>>5] = s;
  __syncthreads();
  if (tid==0){ float x=0.f; for (int i=0;i<8;i++) x+=red[i]; red[0]=x; }
  __syncthreads();
  const float a = e / red[0];

  sa[tid] = a;
  attn_out[b*NS + tid] = a;
  __syncthreads();

  const float* ep = enc + (size_t)b*NS*NH;
  for (int h = tid; h < NH; h += NS){
    float accv = 0.f;
    #pragma unroll 4
    for (int s2=0; s2<NS; s2++) accv += sa[s2]*ep[(size_t)s2*NH + h];
    ctx[b*NH + h] = accv;
  }
}

__global__ void build_x_k(const int* __restrict__ tok, const float* __restrict__ emb,
                          const float* __restrict__ ctx, float* __restrict__ x){
  int i = blockIdx.x*256 + threadIdx.x;
  if (i >= NB*(NE+NH)) return;
  int b = i/(NE+NH), j = i - b*(NE+NH);
  x[i] = (j < NE) ? emb[(size_t)tok[b]*NE + j] : ctx[b*NH + (j-NE)];
}

__global__ void lstm_k(const float* __restrict__ gates, const float* __restrict__ cprev,
                       float* __restrict__ hout, float* __restrict__ cout){
  int i = blockIdx.x*256 + threadIdx.x;   // NB*NH
  int b = i>>10, h = i&1023;
  const float* gr = gates + (size_t)b*4*NH;
  float ig = gr[h], fg = gr[NH+h], gg = gr[2*NH+h], og = gr[3*NH+h];
  float si = 1.f/(1.f+expf(-ig));
  float sf = 1.f/(1.f+expf(-fg));
  float so = 1.f/(1.f+expf(-og));
  float cn = sf*cprev[i] + si*tanhf(gg);
  cout[i] = cn;
  hout[i] = so*tanhf(cn);
}

__global__ void build_cat2_k(const float* __restrict__ h1, const float* __restrict__ ctx,
                             float* __restrict__ cat2){
  int i = blockIdx.x*256 + threadIdx.x;   // NB*2*NH
  int b = i>>11, j = i&2047;
  cat2[i] = (j < NH) ? h1[b*NH + j] : ctx[b*NH + (j-NH)];
}

__global__ void __launch_bounds__(1024) logsoftmax_k(float* __restrict__ pred){
  __shared__ float red[32];
  const int b = blockIdx.x, tid = threadIdx.x;
  float* row = pred + (size_t)b*NV;

  float m = -1e30f;
  for (int i=tid;i<NV;i+=1024) m = fmaxf(m, row[i]);
  #pragma unroll
  for (int o=16;o>0;o>>=1) m = fmaxf(m, __shfl_xor_sync(0xffffffffu, m, o));
  if ((tid&31)==0) red[tid>>5] = m;
  __syncthreads();
  if (tid < 32){
    float x = red[tid];
    #pragma unroll
    for (int o=16;o>0;o>>=1) x = fmaxf(x, __shfl_xor_sync(0xffffffffu, x, o));
    if (tid==0) red[0] = x;
  }
  __syncthreads();
  const float bm = red[0];
  __syncthreads();

  float s = 0.f;
  for (int i=tid;i<NV;i+=1024) s += expf(row[i]-bm);
  #pragma unroll
  for (int o=16;o>0;o>>=1) s += __shfl_xor_sync(0xffffffffu, s, o);
  if ((tid&31)==0) red[tid>>5] = s;
  __syncthreads();
  if (tid < 32){
    float x = red[tid];
    #pragma unroll
    for (int o=16;o>0;o>>=1) x += __shfl_xor_sync(0xffffffffu, x, o);
    if (tid==0) red[0] = x;
  }
  __syncthreads();
  const float lg = bm + logf(red[0]);
  for (int i=tid;i<NV;i+=1024) row[i] = row[i] - lg;
}

// -------- launcher --------
extern "C" void kernel_launch(void* const* d_in, const int* in_sizes, int n_in,
                              void* d_out, int out_size){
  const int*   tok   = (const int*)  d_in[0];
  const float* hidden= (const float*)d_in[1];
  const float* cell  = (const float*)d_in[2];
  const float* enc   = (const float*)d_in[3];
  const float* emb   = (const float*)d_in[4];
  const float* W1w   = (const float*)d_in[5];
  const float* W1b   = (const float*)d_in[6];
  const float* W2w   = (const float*)d_in[7];
  const float* W2b   = (const float*)d_in[8];
  const float* Vw    = (const float*)d_in[9];
  const float* Vb    = (const float*)d_in[10];
  const float* wih0  = (const float*)d_in[11];
  const float* whh0  = (const float*)d_in[12];
  const float* bih0  = (const float*)d_in[13];
  const float* bhh0  = (const float*)d_in[14];
  const float* wih1  = (const float*)d_in[15];
  const float* whh1  = (const float*)d_in[16];
  const float* bih1  = (const float*)d_in[17];
  const float* bhh1  = (const float*)d_in[18];
  const float* fcw   = (const float*)d_in[19];
  const float* fcb   = (const float*)d_in[20];

  float* out    = (float*)d_out;
  float* pred   = out + OFF_PRED;
  float* hid_o  = out + OFF_HID;
  float* cell_o = out + OFF_CELL;
  float* attn_o = out + OFF_ATTN;

  float *q, *spart, *scores, *ctx, *x, *gates, *cat2;
  cudaGetSymbolAddress((void**)&q,      g_q);
  cudaGetSymbolAddress((void**)&spart,  g_spart);
  cudaGetSymbolAddress((void**)&scores, g_scores);
  cudaGetSymbolAddress((void**)&ctx,    g_context);
  cudaGetSymbolAddress((void**)&x,      g_x);
  cudaGetSymbolAddress((void**)&gates,  g_gates);
  cudaGetSymbolAddress((void**)&cat2,   g_cat2);

  dim3 thr(256);

  // 1) q = h_top @ W2^T + W2_b          (128 x 1024 x 1024)
  gemm_tf32<EPI_STORE><<<dim3(NH/BN, 1), thr>>>(
      hidden + (size_t)NB*NH, W2w, q, NB, NH, NH, W2b, nullptr, nullptr, nullptr);

  // 2) fused energy+score partials      (32768 x 1024 x 1024) -- the big one
  gemm_tf32<EPI_ATTN><<<dim3(NH/BN, (NB*NS)/BM), thr>>>(
      enc, W1w, nullptr, NB*NS, NH, NH, W1b, q, Vw, spart);

  // 3) deterministic score reduction (+V_b)
  reduce_scores_k<<<(NB*NS)/256, 256>>>(spart, Vb, scores);

  // 4) softmax over S + context
  softmax_ctx_k<<<NB, NS>>>(scores, enc, attn_o, ctx);

  // 5) x = [emb(tok), context]
  build_x_k<<<(NB*(NE+NH))/256, 256>>>(tok, emb, ctx, x);

  // 6/7) gates0 = x @ w_ih0^T + b_ih0 + h0 @ w_hh0^T + b_hh0
  gemm_tf32<EPI_STORE><<<dim3(4*NH/BN, 1), thr>>>(
      x, wih0, gates, NB, 4*NH, NE+NH, bih0, nullptr, nullptr, nullptr);
  gemm_tf32<EPI_ADD><<<dim3(4*NH/BN, 1), thr>>>(
      hidden, whh0, gates, NB, 4*NH, NH, bhh0, nullptr, nullptr, nullptr);

  // 8) LSTM cell 0 -> (h0', c0') into output hidden/cell layer 0
  lstm_k<<<(NB*NH)/256, 256>>>(gates, cell, hid_o, cell_o);

  // 9/10) gates1 = h0' @ w_ih1^T + b_ih1 + h1 @ w_hh1^T + b_hh1
  gemm_tf32<EPI_STORE><<<dim3(4*NH/BN, 1), thr>>>(
      hid_o, wih1, gates, NB, 4*NH, NH, bih1, nullptr, nullptr, nullptr);
  gemm_tf32<EPI_ADD><<<dim3(4*NH/BN, 1), thr>>>(
      hidden + (size_t)NB*NH, whh1, gates, NB, 4*NH, NH, bhh1, nullptr, nullptr, nullptr);

  // 11) LSTM cell 1 -> layer 1 outputs
  lstm_k<<<(NB*NH)/256, 256>>>(gates, cell + (size_t)NB*NH,
                               hid_o + (size_t)NB*NH, cell_o + (size_t)NB*NH);

  // 12) cat2 = [h1', context]
  build_cat2_k<<<(NB*2*NH)/256, 256>>>(hid_o + (size_t)NB*NH, ctx, cat2);

  // 13) logits = cat2 @ fc_w^T + fc_b   (128 x 32000 x 2048)
  gemm_tf32<EPI_STORE><<<dim3(NV/BN, 1), thr>>>(
      cat2, fcw, pred, NB, NV, 2*NH, fcb, nullptr, nullptr, nullptr);

  // 14) in-place log_softmax
  logsoftmax_k<<<NB, 1024>>>(pred);
}

// round 4
// speedup vs baseline: 2.0792x; 2.0792x over previous
#include <cuda_runtime.h>
#include <cstdint>

#define NB 128
#define NS 256
#define NH 1024
#define NE 512
#define NV 32000
#define NL 2

#define OFF_PRED 0
#define OFF_HID  (NB*NV)
#define OFF_CELL (OFF_HID + NL*NB*NH)
#define OFF_ATTN (OFF_CELL + NL*NB*NH)

#define EPI_STORE 0
#define EPI_ATTN  2

// -------- device scratch --------
__device__ __align__(16) float g_q[NB*NH];
__device__ __align__(16) float g_qpart[4*NB*NH];
__device__ __align__(16) float g_spart[4*NB*NS];
__device__ __align__(16) float g_scores[NB*NS];
__device__ __align__(16) float g_context[NB*NH];
__device__ __align__(16) float g_x0[NB*(NE+2*NH)];   // [emb, ctx, h0_prev] K=2560
__device__ __align__(16) float g_x1[NB*2*NH];        // [h0_new, h1_prev]   K=2048
__device__ __align__(16) float g_gpart[4*NB*4*NH];   // split-K gate partials
__device__ __align__(16) float g_cat2[NB*2*NH];      // [h1_new, ctx]

__device__ __forceinline__ uint32_t smem_u32(const void* p){
  uint32_t a; asm("{ .reg .u64 t; cvta.to.shared.u64 t, %1; cvt.u32.u64 %0, t; }" : "=r"(a) : "l"(p));
  return a;
}
__device__ __forceinline__ void mma8(float* d, const uint32_t* a, const uint32_t* b){
  asm volatile("mma.sync.aligned.m16n8k8.row.col.f32.tf32.tf32.f32 "
    "{%0,%1,%2,%3},{%4,%5,%6,%7},{%8,%9},{%0,%1,%2,%3};"
    : "+f"(d[0]),"+f"(d[1]),"+f"(d[2]),"+f"(d[3])
    : "r"(a[0]),"r"(a[1]),"r"(a[2]),"r"(a[3]),"r"(b[0]),"r"(b[1]));
}

// ============ TF32 mma.sync GEMM: C(M,N) = A(M,K) @ B(N,K)^T ============
// 256 threads. CTA tile 128 x BN. Warp tile 64 x (BN/4).
// B split along K: rows from B1 (stride Ksplit) then B2 (stride K-Ksplit).
// Split-K via blockIdx.z: kOff = z*kLen, C offset by z*M*N (bias must be null).
// Smem rows padded to 80B (20 floats): conflict-free LDS, 16B-aligned cp.async.
template<int BN, int EPI>
__global__ void __launch_bounds__(256,1) gemm_ws(
    const float* __restrict__ A, const float* __restrict__ B1, const float* __restrict__ B2,
    int Ksplit, float* __restrict__ C, int M, int N, int K, int kLen,
    const float* __restrict__ bias,
    const float* __restrict__ qv, const float* __restrict__ vw, float* __restrict__ spart)
{
  constexpr int BM = 128, BK = 16, NSTG = 3;
  constexpr int WN = BN/4;        // warp tile N (64 or 32)
  constexpr int NF = WN/8;        // B frags per warp (8 or 4)
  constexpr int RS = 20;          // smem row stride in floats (80B)
  constexpr int STAGEF = (BM+BN)*RS;        // floats per stage
  constexpr int NCHUNK = (BM+BN)*4;         // 16B chunks per stage
  constexpr int CPT = NCHUNK/256;           // chunks per thread

  extern __shared__ float dsm[];
  __shared__ float sBias[BN];
  __shared__ float sQ[BN], sVw[BN];
  __shared__ float srow[BM];

  const uint32_t smb = smem_u32(dsm);
  const int tid = threadIdx.x, warp = tid>>5, lane = tid&31;
  const int g = lane>>2, tq = lane&3;
  const int wm = (warp&1)*64, wn = (warp>>1)*WN;
  const size_t m0 = (size_t)blockIdx.y*BM;
  const int n0 = blockIdx.x*BN;
  const int kOff = blockIdx.z*kLen;
  const int ktiles = kLen/BK;
  const int K2 = K - Ksplit;

  if (tid < BN){
    sBias[tid] = bias ? bias[n0+tid] : 0.f;
    if (EPI == EPI_ATTN){ sVw[tid] = vw[n0+tid]; sQ[tid] = qv[(m0/NS)*NH + n0 + tid]; }
  }
  if (EPI == EPI_ATTN && tid < BM) srow[tid] = 0.f;

  float acc[4][NF][4];
  #pragma unroll
  for (int i=0;i<4;i++)
    #pragma unroll
    for (int j=0;j<NF;j++)
      #pragma unroll
      for (int k=0;k<4;k++) acc[i][j][k]=0.f;

  auto fill = [&](int s, int t){
    const uint32_t base = smb + (uint32_t)s*STAGEF*4;
    const int kg0 = kOff + t*BK;
    #pragma unroll
    for (int i = 0; i < CPT; i++){
      int c = tid + i*256;
      int row = c>>2, kq = c&3;
      int kg = kg0 + kq*4;
      const float* src;
      if (row < BM) src = A + (m0+row)*(size_t)K + kg;
      else {
        int n = n0 + row - BM;
        if (kg < Ksplit) src = B1 + (size_t)n*Ksplit + kg;
        else             src = B2 + (size_t)n*K2 + (kg - Ksplit);
      }
      uint32_t dst = base + (uint32_t)(row*RS + kq*4)*4;
      asm volatile("cp.async.cg.shared.global [%0], [%1], 16;" :: "r"(dst), "l"(src) : "memory");
    }
    asm volatile("cp.async.commit_group;" ::: "memory");
  };

  fill(0,0); fill(1,1);

  for (int j = 0; j < ktiles; j++){
    asm volatile("cp.async.wait_group 1;" ::: "memory");
    __syncthreads();
    // prefetch tile j+2 into buffer (j+2)%3 (computed at iter j-1, safe after sync)
    if (j+2 < ktiles) fill((j+2)%NSTG, j+2);
    else asm volatile("cp.async.commit_group;" ::: "memory");

    const float* sA = dsm + (j%NSTG)*STAGEF;
    const float* sB = sA + BM*RS;
    #pragma unroll
    for (int kk = 0; kk < 2; kk++){
      const int kb = kk*8;
      uint32_t af[4][4], bf[NF][2];
      #pragma unroll
      for (int mt = 0; mt < 4; mt++){
        int r = wm + mt*16 + g;
        af[mt][0] = __float_as_uint(sA[(r  )*RS + kb+tq  ]);
        af[mt][1] = __float_as_uint(sA[(r+8)*RS + kb+tq  ]);
        af[mt][2] = __float_as_uint(sA[(r  )*RS + kb+tq+4]);
        af[mt][3] = __float_as_uint(sA[(r+8)*RS + kb+tq+4]);
      }
      #pragma unroll
      for (int nt = 0; nt < NF; nt++){
        int c = wn + nt*8 + g;
        bf[nt][0] = __float_as_uint(sB[c*RS + kb+tq  ]);
        bf[nt][1] = __float_as_uint(sB[c*RS + kb+tq+4]);
      }
      #pragma unroll
      for (int mt = 0; mt < 4; mt++)
        #pragma unroll
        for (int nt = 0; nt < NF; nt++)
          mma8(acc[mt][nt], af[mt], bf[nt]);
    }
    __syncthreads();
  }

  if (EPI == EPI_ATTN){
    __syncthreads();
    #pragma unroll
    for (int mt = 0; mt < 4; mt++){
      float p0 = 0.f, p1 = 0.f;
      #pragma unroll
      for (int nt = 0; nt < NF; nt++){
        int c = wn + nt*8 + 2*tq;
        float b0 = sBias[c]   + sQ[c];
        float b1 = sBias[c+1] + sQ[c+1];
        float v0 = sVw[c], v1 = sVw[c+1];
        p0 += tanhf(acc[mt][nt][0]+b0)*v0 + tanhf(acc[mt][nt][1]+b1)*v1;
        p1 += tanhf(acc[mt][nt][2]+b0)*v0 + tanhf(acc[mt][nt][3]+b1)*v1;
      }
      p0 += __shfl_xor_sync(0xffffffffu, p0, 1);
      p0 += __shfl_xor_sync(0xffffffffu, p0, 2);
      p1 += __shfl_xor_sync(0xffffffffu, p1, 1);
      p1 += __shfl_xor_sync(0xffffffffu, p1, 2);
      if (tq == 0){
        atomicAdd(&srow[wm+mt*16+g  ], p0);
        atomicAdd(&srow[wm+mt*16+g+8], p1);
      }
    }
    __syncthreads();
    if (tid < BM) spart[(size_t)blockIdx.x*M + m0 + tid] = srow[tid];
  } else {
    float* Cz = C + (size_t)blockIdx.z*M*N;
    #pragma unroll
    for (int mt = 0; mt < 4; mt++){
      #pragma unroll
      for (int nt = 0; nt < NF; nt++){
        size_t r = m0 + wm + mt*16 + g;
        int c = n0 + wn + nt*8 + 2*tq;
        float b0 = sBias[c - n0], b1 = sBias[c - n0 + 1];
        float2* p0 = (float2*)(Cz + r*N + c);
        float2* p1 = (float2*)(Cz + (r+8)*N + c);
        *p0 = make_float2(acc[mt][nt][0]+b0, acc[mt][nt][1]+b1);
        *p1 = make_float2(acc[mt][nt][2]+b0, acc[mt][nt][3]+b1);
      }
    }
  }
}

// ================= small kernels =================
__global__ void reduce_q_k(const float* __restrict__ qp, const float* __restrict__ w2b,
                           float* __restrict__ q){
  int i = blockIdx.x*256 + threadIdx.x;   // NB*NH
  float s = w2b[i & (NH-1)];
  #pragma unroll
  for (int p = 0; p < 4; p++) s += qp[(size_t)p*NB*NH + i];
  q[i] = s;
}

__global__ void reduce_scores_k(const float* __restrict__ spart, const float* __restrict__ vb,
                                float* __restrict__ scores){
  int m = blockIdx.x*256 + threadIdx.x;
  float s = vb[0];
  #pragma unroll
  for (int j = 0; j < 4; j++) s += spart[(size_t)j*(NB*NS) + m];
  scores[m] = s;
}

__global__ void __launch_bounds__(NS) softmax_k(const float* __restrict__ scores,
                                                float* __restrict__ attn_out){
  __shared__ float red[8];
  const int b = blockIdx.x, tid = threadIdx.x;
  float v = scores[b*NS + tid];
  float m = v;
  #pragma unroll
  for (int o = 16; o > 0; o >>= 1) m = fmaxf(m, __shfl_xor_sync(0xffffffffu, m, o));
  if ((tid&31)==0) red[tid>>5] = m;
  __syncthreads();
  if (tid == 0){ float x = red[0]; for (int i=1;i<8;i++) x = fmaxf(x, red[i]); red[0] = x; }
  __syncthreads();
  const float bm = red[0];
  __syncthreads();
  float e = expf(v - bm), s = e;
  #pragma unroll
  for (int o = 16; o > 0; o >>= 1) s += __shfl_xor_sync(0xffffffffu, s, o);
  if ((tid&31)==0) red[tid>>5] = s;
  __syncthreads();
  if (tid == 0){ float x = 0.f; for (int i=0;i<8;i++) x += red[i]; red[0] = x; }
  __syncthreads();
  attn_out[b*NS + tid] = e / red[0];
}

__global__ void __launch_bounds__(128) ctx_k(const float* __restrict__ attn,
                                             const float* __restrict__ enc, float* __restrict__ ctx){
  __shared__ float sa[NS];
  const int b = blockIdx.x, hc = blockIdx.y, tid = threadIdx.x;
  sa[tid]     = attn[b*NS + tid];
  sa[tid+128] = attn[b*NS + tid + 128];
  __syncthreads();
  const int h = hc*128 + tid;
  const float* ep = enc + (size_t)b*NS*NH + h;
  float acc = 0.f;
  #pragma unroll 4
  for (int s = 0; s < NS; s++) acc += sa[s]*ep[(size_t)s*NH];
  ctx[b*NH + h] = acc;
}

__global__ void build_x0_k(const int* __restrict__ tok, const float* __restrict__ emb,
                           const float* __restrict__ ctx, const float* __restrict__ hidden,
                           float* __restrict__ x0){
  int i = blockIdx.x*256 + threadIdx.x;
  if (i >= NB*(NE+2*NH)) return;
  int b = i/(NE+2*NH), j = i - b*(NE+2*NH);
  float v;
  if (j < NE)         v = emb[(size_t)tok[b]*NE + j];
  else if (j < NE+NH) v = ctx[b*NH + (j-NE)];
  else                v = hidden[b*NH + (j-NE-NH)];
  x0[i] = v;
}

__global__ void build_x1_k(const float* __restrict__ h0new, const float* __restrict__ hidden,
                           float* __restrict__ x1){
  int i = blockIdx.x*256 + threadIdx.x;
  int b = i >> 11, j = i & 2047;
  x1[i] = (j < NH) ? h0new[b*NH + j] : hidden[(size_t)NB*NH + b*NH + (j-NH)];
}

// sums 4 split-K gate partials + both biases, then applies LSTM cell
__global__ void lstm_k(const float* __restrict__ gp, const float* __restrict__ bih,
                       const float* __restrict__ bhh, const float* __restrict__ cprev,
                       float* __restrict__ hout, float* __restrict__ cout){
  int i = blockIdx.x*256 + threadIdx.x;   // NB*NH
  int b = i >> 10, h = i & 1023;
  const size_t base = (size_t)b*4*NH;
  float ig = bih[h]      + bhh[h];
  float fg = bih[NH+h]   + bhh[NH+h];
  float gg = bih[2*NH+h] + bhh[2*NH+h];
  float og = bih[3*NH+h] + bhh[3*NH+h];
  #pragma unroll
  for (int p = 0; p < 4; p++){
    const float* gr = gp + (size_t)p*NB*4*NH + base;
    ig += gr[h]; fg += gr[NH+h]; gg += gr[2*NH+h]; og += gr[3*NH+h];
  }
  float si = 1.f/(1.f+expf(-ig));
  float sf = 1.f/(1.f+expf(-fg));
  float so = 1.f/(1.f+expf(-og));
  float cn = sf*cprev[i] + si*tanhf(gg);
  cout[i] = cn;
  hout[i] = so*tanhf(cn);
}

__global__ void build_cat2_k(const float* __restrict__ h1, const float* __restrict__ ctx,
                             float* __restrict__ cat2){
  int i = blockIdx.x*256 + threadIdx.x;
  int b = i >> 11, j = i & 2047;
  cat2[i] = (j < NH) ? h1[b*NH + j] : ctx[b*NH + (j-NH)];
}

__global__ void __launch_bounds__(1024) logsoftmax_k(float* __restrict__ pred){
  __shared__ float red[32];
  const int b = blockIdx.x, tid = threadIdx.x;
  float* row = pred + (size_t)b*NV;
  float m = -1e30f;
  for (int i = tid; i < NV; i += 1024) m = fmaxf(m, row[i]);
  #pragma unroll
  for (int o = 16; o > 0; o >>= 1) m = fmaxf(m, __shfl_xor_sync(0xffffffffu, m, o));
  if ((tid&31)==0) red[tid>>5] = m;
  __syncthreads();
  if (tid < 32){
    float x = red[tid];
    #pragma unroll
    for (int o = 16; o > 0; o >>= 1) x = fmaxf(x, __shfl_xor_sync(0xffffffffu, x, o));
    if (tid == 0) red[0] = x;
  }
  __syncthreads();
  const float bm = red[0];
  __syncthreads();
  float s = 0.f;
  for (int i = tid; i < NV; i += 1024) s += expf(row[i] - bm);
  #pragma unroll
  for (int o = 16; o > 0; o >>= 1) s += __shfl_xor_sync(0xffffffffu, s, o);
  if ((tid&31)==0) red[tid>>5] = s;
  __syncthreads();
  if (tid < 32){
    float x = red[tid];
    #pragma unroll
    for (int o = 16; o > 0; o >>= 1) x += __shfl_xor_sync(0xffffffffu, x, o);
    if (tid == 0) red[0] = x;
  }
  __syncthreads();
  const float lg = bm + logf(red[0]);
  for (int i = tid; i < NV; i += 1024) row[i] = row[i] - lg;
}

// ================= launcher =================
extern "C" void kernel_launch(void* const* d_in, const int* in_sizes, int n_in,
                              void* d_out, int out_size){
  const int*   tok   = (const int*)  d_in[0];
  const float* hidden= (const float*)d_in[1];
  const float* cell  = (const float*)d_in[2];
  const float* enc   = (const float*)d_in[3];
  const float* emb   = (const float*)d_in[4];
  const float* W1w   = (const float*)d_in[5];
  const float* W1b   = (const float*)d_in[6];
  const float* W2w   = (const float*)d_in[7];
  const float* W2b   = (const float*)d_in[8];
  const float* Vw    = (const float*)d_in[9];
  const float* Vb    = (const float*)d_in[10];
  const float* wih0  = (const float*)d_in[11];
  const float* whh0  = (const float*)d_in[12];
  const float* bih0  = (const float*)d_in[13];
  const float* bhh0  = (const float*)d_in[14];
  const float* wih1  = (const float*)d_in[15];
  const float* whh1  = (const float*)d_in[16];
  const float* bih1  = (const float*)d_in[17];
  const float* bhh1  = (const float*)d_in[18];
  const float* fcw   = (const float*)d_in[19];
  const float* fcb   = (const float*)d_in[20];

  float* out    = (float*)d_out;
  float* pred   = out + OFF_PRED;
  float* hid_o  = out + OFF_HID;
  float* cell_o = out + OFF_CELL;
  float* attn_o = out + OFF_ATTN;

  float *q, *qp, *spart, *scores, *ctx, *x0, *x1, *gp, *cat2;
  cudaGetSymbolAddress((void**)&q,      g_q);
  cudaGetSymbolAddress((void**)&qp,     g_qpart);
  cudaGetSymbolAddress((void**)&spart,  g_spart);
  cudaGetSymbolAddress((void**)&scores, g_scores);
  cudaGetSymbolAddress((void**)&ctx,    g_context);
  cudaGetSymbolAddress((void**)&x0,     g_x0);
  cudaGetSymbolAddress((void**)&x1,     g_x1);
  cudaGetSymbolAddress((void**)&gp,     g_gpart);
  cudaGetSymbolAddress((void**)&cat2,   g_cat2);

  const int smN128 = (128+128)*20*4*3;   // 61440 B
  const int smN256 = (128+256)*20*4*3;   // 92160 B
  cudaFuncSetAttribute(gemm_ws<128,EPI_STORE>, cudaFuncAttributeMaxDynamicSharedMemorySize, smN128);
  cudaFuncSetAttribute(gemm_ws<256,EPI_STORE>, cudaFuncAttributeMaxDynamicSharedMemorySize, smN256);
  cudaFuncSetAttribute(gemm_ws<256,EPI_ATTN>,  cudaFuncAttributeMaxDynamicSharedMemorySize, smN256);

  // 1) q partials: h_top @ W2^T  (128x1024x1024, split-K 4)
  gemm_ws<128,EPI_STORE><<<dim3(NH/128,1,4), 256, smN128>>>(
      hidden + (size_t)NB*NH, W2w, W2w, NH, qp, NB, NH, NH, NH/4,
      nullptr, nullptr, nullptr, nullptr);
  reduce_q_k<<<(NB*NH)/256, 256>>>(qp, W2b, q);

  // 2) fused energy + score partials (32768x1024x1024)
  gemm_ws<256,EPI_ATTN><<<dim3(NH/256, (NB*NS)/128, 1), 256, smN256>>>(
      enc, W1w, W1w, NH, nullptr, NB*NS, NH, NH, NH,
      W1b, q, Vw, spart);

  // 3) score reduction (+V_b)
  reduce_scores_k<<<(NB*NS)/256, 256>>>(spart, Vb, scores);

  // 4) softmax over S
  softmax_k<<<NB, NS>>>(scores, attn_o);

  // 5) context
  ctx_k<<<dim3(NB, NH/128), 128>>>(attn_o, enc, ctx);

  // 6) x0 = [emb, ctx, h0_prev]
  build_x0_k<<<(NB*(NE+2*NH))/256, 256>>>(tok, emb, ctx, hidden, x0);

  // 7) gates0 partials: x0 @ [wih0|whh0]^T  (128x4096x2560, split-K 4)
  gemm_ws<128,EPI_STORE><<<dim3(4*NH/128,1,4), 256, smN128>>>(
      x0, wih0, whh0, NE+NH, gp, NB, 4*NH, NE+2*NH, (NE+2*NH)/4,
      nullptr, nullptr, nullptr, nullptr);

  // 8) LSTM cell 0 (sums partials + biases)
  lstm_k<<<(NB*NH)/256, 256>>>(gp, bih0, bhh0, cell, hid_o, cell_o);

  // 9) x1 = [h0_new, h1_prev]
  build_x1_k<<<(NB*2*NH)/256, 256>>>(hid_o, hidden, x1);

  // 10) gates1 partials: x1 @ [wih1|whh1]^T  (128x4096x2048, split-K 4)
  gemm_ws<128,EPI_STORE><<<dim3(4*NH/128,1,4), 256, smN128>>>(
      x1, wih1, whh1, NH, gp, NB, 4*NH, 2*NH, (2*NH)/4,
      nullptr, nullptr, nullptr, nullptr);

  // 11) LSTM cell 1
  lstm_k<<<(NB*NH)/256, 256>>>(gp, bih1, bhh1, cell + (size_t)NB*NH,
                               hid_o + (size_t)NB*NH, cell_o + (size_t)NB*NH);

  // 12) cat2 = [h1_new, ctx]
  build_cat2_k<<<(NB*2*NH)/256, 256>>>(hid_o + (size_t)NB*NH, ctx, cat2);

  // 13) logits = cat2 @ fc_w^T + fc_b  (128x32000x2048)
  gemm_ws<256,EPI_STORE><<<dim3(NV/256,1,1), 256, smN256>>>(
      cat2, fcw, fcw, 2*NH, pred, NB, NV, 2*NH, 2*NH,
      fcb, nullptr, nullptr, nullptr);

  // 14) log_softmax in place
  logsoftmax_k<<<NB, 1024>>>(pred);
}